// round 5
// baseline (speedup 1.0000x reference)
#include <cuda_runtime.h>
#include <math.h>

// ---------------- problem constants ----------------
#define BATCH 8
#define SEQL 512
#define NFEAT 16
#define DMODEL 512
#define FDIM 256          // L/2
#define HID 1024          // 4*F
#define NEXP 43
#define TOPK 5
#define TOTROWS 1657
#define EMB_ELEMS 108593152LL   // 8*16*1657*512
#define KS1 32            // k-split for mlp1 (256/32 = 8 per block)
#define KS2 64            // h-split for mlp2 (1024/64 = 16 per block)

__constant__ int c_P[NEXP] = {
  2,3,4,5,6,7,8,9,10,11,12,13,14,15,16,17,18,19,20,21,22,23,24,25,26,
  28,30,32,34,36,39,42,46,51,56,64,73,85,102,128,170,256,512};
__constant__ int c_OFF[NEXP+1] = {
  0,256,427,555,658,744,818,882,939,991,1038,1081,1121,1158,1193,1225,
  1256,1285,1312,1338,1363,1387,1410,1432,1453,1473,1492,1510,1526,1542,
  1557,1571,1584,1596,1607,1617,1625,1633,1640,1646,1650,1654,1656,1657};

// ---------------- device scratch ----------------
__device__ float g_xr[BATCH][FDIM];
__device__ float g_xi[BATCH][FDIM];
__device__ float g_p1r[KS1][BATCH][HID];    // mlp1 partials
__device__ float g_p1i[KS1][BATCH][HID];
__device__ float g_p2r[KS2][BATCH][FDIM];   // mlp2 partials
__device__ float g_p2i[KS2][BATCH][FDIM];
__device__ float g_mask[BATCH][NEXP];
__device__ float g_feat[NFEAT][256];   // first half of d_model, depends on c
__device__ float g_pos[256][256];      // second half, depends on patch idx j

// ---------------- K1: gate1 (blocks 0-7) + pos tables (blocks 8-143) -------
__global__ void __launch_bounds__(512)
gate1_pos_kernel(const float* __restrict__ x,
                 const float* __restrict__ w_start,
                 const float* __restrict__ b_start) {
    if (blockIdx.x >= 8) {
        // positional tables, fp64 to match numpy
        int idx = (blockIdx.x - 8) * 512 + threadIdx.x;   // 0 .. 69631
        if (idx < NFEAT * 256) {
            int c = idx >> 8, i = idx & 255;
            double div = pow(10000.0, (double)(2 * (i >> 1)) / 256.0);
            double a = (double)c / div;
            g_feat[c][i] = (float)((i & 1) ? cos(a) : sin(a));
        } else {
            int k2 = idx - NFEAT * 256;
            int j = k2 >> 8, i = k2 & 255;
            double div = pow(10000.0, (double)(2 * (i >> 1)) / 256.0);
            double a = (double)j / div;
            g_pos[j][i] = (float)((i & 1) ? cos(a) : sin(a));
        }
        return;
    }
    // ---- gate1: start_fc + direct rFFT (ortho, drop DC), 512 threads ----
    __shared__ float xs[SEQL];
    __shared__ float2 tw[SEQL];
    __shared__ float2 ps[SEQL];
    __shared__ float ws[NFEAT];
    int b = blockIdx.x, t = threadIdx.x;
    if (t < NFEAT) ws[t] = w_start[t];
    {
        float s, c;
        sincospif((float)t * (1.0f / 256.0f), &s, &c);  // angle = 2*pi*t/512
        tw[t] = make_float2(c, s);
    }
    __syncthreads();
    {
        const float* xp = x + (((size_t)b * SEQL + t) << 4);
        float s = b_start[0];
        #pragma unroll
        for (int c = 0; c < NFEAT; c++) s = fmaf(xp[c], ws[c], s);
        xs[t] = s;
    }
    __syncthreads();
    int k  = (t & 255) + 1;                          // k = 1..256 (DC dropped)
    int l0 = (t >> 8) << 8;                          // 0 or 256
    float re = 0.f, im = 0.f;
    int m = (k * l0) & 511;
    #pragma unroll 8
    for (int i = 0; i < 256; i++) {
        float xv = xs[l0 + i];
        float2 w = tw[m];
        re = fmaf(xv,  w.x, re);
        im = fmaf(xv, -w.y, im);
        m = (m + k) & 511;
    }
    ps[t] = make_float2(re, im);
    __syncthreads();
    if (t < 256) {
        const float sc = 0.04419417382415922f;       // 1/sqrt(512)
        float2 lo = ps[t], hi = ps[t + 256];
        g_xr[b][t] = (lo.x + hi.x) * sc;
        g_xi[b][t] = (lo.y + hi.y) * sc;
    }
}

// ---------------- K2: complex layer 1 partials (all batches per thread) ----
// grid (HID/256=4, KS1=32), 256 threads. Each thread: one h, 8-k slice, 8 b.
__global__ void __launch_bounds__(256)
mlp1_part_kernel(const float* __restrict__ w1) {
    const int kz = blockIdx.y;
    const int h  = blockIdx.x * 256 + threadIdx.x;   // 0..1023
    const int KSL = FDIM / KS1;                      // 8
    const int k0 = kz * KSL;
    __shared__ float sxr[BATCH][KSL], sxi[BATCH][KSL];
    if (threadIdx.x < BATCH * KSL) {
        int b = threadIdx.x >> 3, k = threadIdx.x & 7;
        sxr[b][k] = g_xr[b][k0 + k];
        sxi[b][k] = g_xi[b][k0 + k];
    }
    __syncthreads();
    const float* w1r = w1 + (size_t)k0 * HID;
    const float* w1i = w1 + (size_t)(FDIM + k0) * HID;
    float ar[BATCH], ai[BATCH];
    #pragma unroll
    for (int b = 0; b < BATCH; b++) { ar[b] = 0.f; ai[b] = 0.f; }
    #pragma unroll
    for (int k = 0; k < KSL; k++) {
        float wr = w1r[(size_t)k * HID + h];
        float wi = w1i[(size_t)k * HID + h];
        #pragma unroll
        for (int b = 0; b < BATCH; b++) {
            float xr = sxr[b][k], xi = sxi[b][k];
            ar[b] = fmaf(xr, wr, fmaf(-xi, wi, ar[b]));
            ai[b] = fmaf(xi, wr, fmaf( xr, wi, ai[b]));
        }
    }
    #pragma unroll
    for (int b = 0; b < BATCH; b++) {
        g_p1r[kz][b][h] = ar[b];
        g_p1i[kz][b][h] = ai[b];
    }
}

// ---------------- K3: reduce o1 slice + complex layer 2 partials -----------
// grid (KS2=64), 256 threads. Stage 1: build o1[h0..h0+16) for 8 batches.
// Stage 2: each thread one f, 16-h slice, 8 batches.
__global__ void __launch_bounds__(256)
mlp2_part_kernel(const float* __restrict__ w2, const float* __restrict__ b1) {
    const int hz = blockIdx.x;
    const int HS = HID / KS2;                        // 16
    const int h0 = hz * HS;
    __shared__ float s1r[BATCH][HS], s1i[BATCH][HS];
    if (threadIdx.x < BATCH * HS) {                  // 128 threads
        int b = threadIdx.x >> 4, hl = threadIdx.x & 15;
        int h = h0 + hl;
        float ar = 0.f, ai = 0.f;
        #pragma unroll
        for (int kz = 0; kz < KS1; kz++) {
            ar += g_p1r[kz][b][h];
            ai += g_p1i[kz][b][h];
        }
        ar += b1[h]; ai += b1[HID + h];
        s1r[b][hl] = fmaxf(ar, 0.f);
        s1i[b][hl] = fmaxf(ai, 0.f);
    }
    __syncthreads();
    const int f = threadIdx.x;
    const float* w2r = w2 + (size_t)h0 * FDIM;
    const float* w2i = w2 + (size_t)(HID + h0) * FDIM;
    float ar[BATCH], ai[BATCH];
    #pragma unroll
    for (int b = 0; b < BATCH; b++) { ar[b] = 0.f; ai[b] = 0.f; }
    #pragma unroll
    for (int h = 0; h < HS; h++) {
        float wr = w2r[(size_t)h * FDIM + f];
        float wi = w2i[(size_t)h * FDIM + f];
        #pragma unroll
        for (int b = 0; b < BATCH; b++) {
            float xr = s1r[b][h], xi = s1i[b][h];
            ar[b] = fmaf(xr, wr, fmaf(-xi, wi, ar[b]));
            ai[b] = fmaf(xi, wr, fmaf( xr, wi, ai[b]));
        }
    }
    #pragma unroll
    for (int b = 0; b < BATCH; b++) {
        g_p2r[hz][b][f] = ar[b];
        g_p2i[hz][b][f] = ai[b];
    }
}

// ---------------- K4: reduce + softshrink + amp + logits + top-5 ----------
// grid (BATCH), 512 threads. 8-thread group per expert for logits.
__global__ void __launch_bounds__(512)
gate2_kernel(const float* __restrict__ b2, const float* __restrict__ w_gate,
             float* __restrict__ gates_out) {
    int b = blockIdx.x, t = threadIdx.x;
    __shared__ float samp[FDIM];
    __shared__ float slog[NEXP];
    if (t < FDIM) {
        int f = t;
        float ar = 0.f, ai = 0.f;
        #pragma unroll
        for (int hz = 0; hz < KS2; hz++) {
            ar += g_p2r[hz][b][f];
            ai += g_p2i[hz][b][f];
        }
        ar += b2[f]; ai += b2[FDIM + f];
        ar = (ar > 0.01f) ? ar - 0.01f : ((ar < -0.01f) ? ar + 0.01f : 0.f);
        ai = (ai > 0.01f) ? ai - 0.01f : ((ai < -0.01f) ? ai + 0.01f : 0.f);
        samp[f] = sqrtf(fmaf(ar, ar, fmaf(ai, ai, 1e-12f)));
    }
    __syncthreads();
    // logits: 64 groups of 8 threads; ALL threads run the shfl (full-warp
    // convergence), groups >= NEXP just compute zeros and discard.
    int g = t >> 3, lg = t & 7;
    float acc = 0.f;
    if (g < NEXP) {
        #pragma unroll
        for (int i = 0; i < 32; i++) {
            int k = lg + i * 8;
            acc = fmaf(samp[k], w_gate[k * NEXP + g], acc);
        }
    }
    acc += __shfl_down_sync(0xffffffffu, acc, 4, 8);
    acc += __shfl_down_sync(0xffffffffu, acc, 2, 8);
    acc += __shfl_down_sync(0xffffffffu, acc, 1, 8);
    if (lg == 0 && g < NEXP) slog[g] = acc;
    __syncthreads();
    if (t == 0) {
        float v[NEXP];
        for (int e = 0; e < NEXP; e++) v[e] = slog[e];
        int   idx[TOPK];
        float val[TOPK];
        for (int tt = 0; tt < TOPK; tt++) {
            int bi = 0; float bv = v[0];
            for (int e = 1; e < NEXP; e++) if (v[e] > bv) { bv = v[e]; bi = e; }
            idx[tt] = bi; val[tt] = bv; v[bi] = -3.4e38f;
        }
        float mx = val[0], sum = 0.f, ex[TOPK];
        for (int tt = 0; tt < TOPK; tt++) { ex[tt] = expf(val[tt] - mx); sum += ex[tt]; }
        for (int e = 0; e < NEXP; e++) { gates_out[b * NEXP + e] = 0.f; g_mask[b][e] = 0.f; }
        for (int tt = 0; tt < TOPK; tt++) {
            gates_out[b * NEXP + idx[tt]] = ex[tt] / sum;
            g_mask[b][idx[tt]] = 1.0f;
        }
    }
}

// ---------------- K5: main patch-embedding / zero-fill ----------------
// grid (1657, 8): x = patch-row (reversed: big p first), y = batch.
// 512 threads: tid = z*256 + col (z = d-half, col = d within half).
__global__ void __launch_bounds__(512)
embed_kernel(const float* __restrict__ x, const float* __restrict__ Wv,
             float* __restrict__ out) {
    const int r = (TOTROWS - 1) - blockIdx.x;     // largest p scheduled first
    const int b = blockIdx.y;
    const int tid = threadIdx.x;
    const int z = tid >> 8, col = tid & 255;

    // expert lookup (constant-mem scan, uniform)
    int e = 0;
    while (c_OFF[e + 1] <= r) e++;
    const int p = c_P[e];
    const int j = r - c_OFF[e];

    const size_t cstride = (size_t)TOTROWS * DMODEL;
    float* outb = out + ((size_t)(b * NFEAT) * TOTROWS + r) * DMODEL;

    if (g_mask[b][e] == 0.f) {
        // zero-fill 16 rows x 512 cols, float4 (NFEAT*128 = 2048 vec4)
        float4 zz = make_float4(0.f, 0.f, 0.f, 0.f);
        #pragma unroll
        for (int idx = tid; idx < NFEAT * 128; idx += 512) {
            int c = idx >> 7, v = idx & 127;
            *(float4*)(outb + (size_t)c * cstride + v * 4) = zz;
        }
        return;
    }

    extern __shared__ float xsm[];                // p*16 floats (<=32KB)
    {
        const float4* x4 = (const float4*)x;
        float4* xsm4 = (float4*)xsm;
        for (int idx = tid; idx < p * 4; idx += 512) {
            int q = idx >> 2, v = idx & 3;
            int l = j * p + q; if (l > SEQL - 1) l = SEQL - 1;   // edge pad
            xsm4[idx] = x4[(((size_t)b * SEQL + l) << 2) + v];
        }
    }
    __syncthreads();

    float acc[NFEAT];
    #pragma unroll
    for (int c = 0; c < NFEAT; c++) acc[c] = 0.f;

    const float* wv = Wv + (size_t)e * SEQL * DMODEL + tid;
    #pragma unroll 4
    for (int q = 0; q < p; q++) {
        float w = wv[(size_t)q * DMODEL];
        const float* xq = xsm + q * NFEAT;
        #pragma unroll
        for (int c = 0; c < NFEAT; c++) acc[c] = fmaf(xq[c], w, acc[c]);
    }

    if (z == 0) {
        #pragma unroll
        for (int c = 0; c < NFEAT; c++)
            outb[(size_t)c * cstride + tid] = acc[c] + g_feat[c][col];
    } else {
        float pe = g_pos[j][col];
        #pragma unroll
        for (int c = 0; c < NFEAT; c++)
            outb[(size_t)c * cstride + tid] = acc[c] + pe;
    }
}

// ---------------- launch ----------------
extern "C" void kernel_launch(void* const* d_in, const int* in_sizes, int n_in,
                              void* d_out, int out_size) {
    const float* x       = (const float*)d_in[0];
    const float* w_start = (const float*)d_in[1];
    const float* b_start = (const float*)d_in[2];
    const float* w1      = (const float*)d_in[3];
    const float* b1      = (const float*)d_in[4];
    const float* w2      = (const float*)d_in[5];
    const float* b2      = (const float*)d_in[6];
    const float* w_gate  = (const float*)d_in[7];
    const float* Wv      = (const float*)d_in[8];
    float* out = (float*)d_out;
    float* gates_out = out + EMB_ELEMS;

    gate1_pos_kernel<<<8 + 136, 512>>>(x, w_start, b_start);
    mlp1_part_kernel<<<dim3(HID / 256, KS1), 256>>>(w1);
    mlp2_part_kernel<<<KS2, 256>>>(w2, b1);
    gate2_kernel<<<BATCH, 512>>>(b2, w_gate, gates_out);
    embed_kernel<<<dim3(TOTROWS, BATCH), 512, 32768>>>(x, Wv, out);
}

// round 6
// speedup vs baseline: 1.5683x; 1.5683x over previous
#include <cuda_runtime.h>
#include <math.h>

// ---------------- problem constants ----------------
#define BATCH 8
#define SEQL 512
#define NFEAT 16
#define DMODEL 512
#define FDIM 256          // L/2
#define HID 1024          // 4*F
#define NEXP 43
#define TOPK 5
#define TOTROWS 1657
#define EMB_ELEMS 108593152LL   // 8*16*1657*512
#define KS1 16            // k-split for mlp1 (256/16 = 16 per block)
#define KS2 32            // h-split for mlp2 (1024/32 = 32 per block)

__constant__ int c_P[NEXP] = {
  2,3,4,5,6,7,8,9,10,11,12,13,14,15,16,17,18,19,20,21,22,23,24,25,26,
  28,30,32,34,36,39,42,46,51,56,64,73,85,102,128,170,256,512};
__constant__ int c_OFF[NEXP+1] = {
  0,256,427,555,658,744,818,882,939,991,1038,1081,1121,1158,1193,1225,
  1256,1285,1312,1338,1363,1387,1410,1432,1453,1473,1492,1510,1526,1542,
  1557,1571,1584,1596,1607,1617,1625,1633,1640,1646,1650,1654,1656,1657};

// ---------------- device scratch ----------------
__device__ float g_xr[BATCH][FDIM];
__device__ float g_xi[BATCH][FDIM];
__device__ float g_p1r[KS1][BATCH][HID];    // mlp1 partials
__device__ float g_p1i[KS1][BATCH][HID];
__device__ float g_p2r[KS2][BATCH][FDIM];   // mlp2 partials
__device__ float g_p2i[KS2][BATCH][FDIM];
__device__ float g_mask[BATCH][NEXP];
__device__ float g_feat[NFEAT][256];   // first half of d_model, depends on c
__device__ float g_pos[256][256];      // second half, depends on patch idx j

// ---------------- K1: gate1 (blocks 0-7) + pos tables (blocks 8-143) -------
__global__ void __launch_bounds__(512)
gate1_pos_kernel(const float* __restrict__ x,
                 const float* __restrict__ w_start,
                 const float* __restrict__ b_start) {
    if (blockIdx.x >= 8) {
        // positional tables, fp64 to match numpy
        int idx = (blockIdx.x - 8) * 512 + threadIdx.x;   // 0 .. 69631
        if (idx < NFEAT * 256) {
            int c = idx >> 8, i = idx & 255;
            double div = pow(10000.0, (double)(2 * (i >> 1)) / 256.0);
            double a = (double)c / div;
            g_feat[c][i] = (float)((i & 1) ? cos(a) : sin(a));
        } else {
            int k2 = idx - NFEAT * 256;
            int j = k2 >> 8, i = k2 & 255;
            double div = pow(10000.0, (double)(2 * (i >> 1)) / 256.0);
            double a = (double)j / div;
            g_pos[j][i] = (float)((i & 1) ? cos(a) : sin(a));
        }
        return;
    }
    // ---- gate1: start_fc + direct rFFT (ortho, drop DC), 512 threads ----
    __shared__ float xs[SEQL];
    __shared__ float2 tw[SEQL];
    __shared__ float2 ps[SEQL];
    __shared__ float ws[NFEAT];
    int b = blockIdx.x, t = threadIdx.x;
    if (t < NFEAT) ws[t] = w_start[t];
    {
        float s, c;
        sincospif((float)t * (1.0f / 256.0f), &s, &c);  // angle = 2*pi*t/512
        tw[t] = make_float2(c, s);
    }
    __syncthreads();
    {
        const float* xp = x + (((size_t)b * SEQL + t) << 4);
        float s = b_start[0];
        #pragma unroll
        for (int c = 0; c < NFEAT; c++) s = fmaf(xp[c], ws[c], s);
        xs[t] = s;
    }
    __syncthreads();
    int k  = (t & 255) + 1;                          // k = 1..256 (DC dropped)
    int l0 = (t >> 8) << 8;                          // 0 or 256
    float re = 0.f, im = 0.f;
    int m = (k * l0) & 511;
    #pragma unroll 8
    for (int i = 0; i < 256; i++) {
        float xv = xs[l0 + i];
        float2 w = tw[m];
        re = fmaf(xv,  w.x, re);
        im = fmaf(xv, -w.y, im);
        m = (m + k) & 511;
    }
    ps[t] = make_float2(re, im);
    __syncthreads();
    if (t < 256) {
        const float sc = 0.04419417382415922f;       // 1/sqrt(512)
        float2 lo = ps[t], hi = ps[t + 256];
        g_xr[b][t] = (lo.x + hi.x) * sc;
        g_xi[b][t] = (lo.y + hi.y) * sc;
    }
}

// ---------------- K2: complex layer 1 partials (all batches per thread) ----
// grid (HID/256=4, KS1=16), 256 threads. Each thread: one h, 16-k slice, 8 b.
__global__ void __launch_bounds__(256)
mlp1_part_kernel(const float* __restrict__ w1) {
    const int kz = blockIdx.y;
    const int h  = blockIdx.x * 256 + threadIdx.x;   // 0..1023
    const int KSL = FDIM / KS1;                      // 16
    const int k0 = kz * KSL;
    __shared__ float sxr[BATCH][KSL], sxi[BATCH][KSL];
    if (threadIdx.x < BATCH * KSL) {
        int b = threadIdx.x >> 4, k = threadIdx.x & 15;
        sxr[b][k] = g_xr[b][k0 + k];
        sxi[b][k] = g_xi[b][k0 + k];
    }
    __syncthreads();
    const float* w1r = w1 + (size_t)k0 * HID;
    const float* w1i = w1 + (size_t)(FDIM + k0) * HID;
    float ar[BATCH], ai[BATCH];
    #pragma unroll
    for (int b = 0; b < BATCH; b++) { ar[b] = 0.f; ai[b] = 0.f; }
    #pragma unroll
    for (int k = 0; k < KSL; k++) {
        float wr = w1r[(size_t)k * HID + h];
        float wi = w1i[(size_t)k * HID + h];
        #pragma unroll
        for (int b = 0; b < BATCH; b++) {
            float xr = sxr[b][k], xi = sxi[b][k];
            ar[b] = fmaf(xr, wr, fmaf(-xi, wi, ar[b]));
            ai[b] = fmaf(xi, wr, fmaf( xr, wi, ai[b]));
        }
    }
    #pragma unroll
    for (int b = 0; b < BATCH; b++) {
        g_p1r[kz][b][h] = ar[b];
        g_p1i[kz][b][h] = ai[b];
    }
}

// ---------------- K3: reduce o1 slice + complex layer 2 partials -----------
// grid (KS2=32), 256 threads. Stage 1: build o1[h0..h0+32) for 8 batches.
// Stage 2: each thread one f, 32-h slice, 8 batches.
__global__ void __launch_bounds__(256)
mlp2_part_kernel(const float* __restrict__ w2, const float* __restrict__ b1) {
    const int hz = blockIdx.x;
    const int HS = HID / KS2;                        // 32
    const int h0 = hz * HS;
    __shared__ float s1r[BATCH][HS], s1i[BATCH][HS];
    {
        int b = threadIdx.x >> 5, hl = threadIdx.x & 31;   // exactly 256 = 8*32
        int h = h0 + hl;
        float ar = 0.f, ai = 0.f;
        #pragma unroll
        for (int kz = 0; kz < KS1; kz++) {
            ar += g_p1r[kz][b][h];
            ai += g_p1i[kz][b][h];
        }
        ar += b1[h]; ai += b1[HID + h];
        s1r[b][hl] = fmaxf(ar, 0.f);
        s1i[b][hl] = fmaxf(ai, 0.f);
    }
    __syncthreads();
    const int f = threadIdx.x;
    const float* w2r = w2 + (size_t)h0 * FDIM;
    const float* w2i = w2 + (size_t)(HID + h0) * FDIM;
    float ar[BATCH], ai[BATCH];
    #pragma unroll
    for (int b = 0; b < BATCH; b++) { ar[b] = 0.f; ai[b] = 0.f; }
    #pragma unroll
    for (int h = 0; h < HS; h++) {
        float wr = w2r[(size_t)h * FDIM + f];
        float wi = w2i[(size_t)h * FDIM + f];
        #pragma unroll
        for (int b = 0; b < BATCH; b++) {
            float xr = s1r[b][h], xi = s1i[b][h];
            ar[b] = fmaf(xr, wr, fmaf(-xi, wi, ar[b]));
            ai[b] = fmaf(xi, wr, fmaf( xr, wi, ai[b]));
        }
    }
    #pragma unroll
    for (int b = 0; b < BATCH; b++) {
        g_p2r[hz][b][f] = ar[b];
        g_p2i[hz][b][f] = ai[b];
    }
}

// ---------------- K4: reduce + softshrink + amp + logits + top-5 ----------
// grid (BATCH), 512 threads. 8-thread group per expert for logits.
__global__ void __launch_bounds__(512)
gate2_kernel(const float* __restrict__ b2, const float* __restrict__ w_gate,
             float* __restrict__ gates_out) {
    int b = blockIdx.x, t = threadIdx.x;
    __shared__ float samp[FDIM];
    __shared__ float slog[NEXP];
    if (t < FDIM) {
        int f = t;
        float ar = 0.f, ai = 0.f;
        #pragma unroll
        for (int hz = 0; hz < KS2; hz++) {
            ar += g_p2r[hz][b][f];
            ai += g_p2i[hz][b][f];
        }
        ar += b2[f]; ai += b2[FDIM + f];
        ar = (ar > 0.01f) ? ar - 0.01f : ((ar < -0.01f) ? ar + 0.01f : 0.f);
        ai = (ai > 0.01f) ? ai - 0.01f : ((ai < -0.01f) ? ai + 0.01f : 0.f);
        samp[f] = sqrtf(fmaf(ar, ar, fmaf(ai, ai, 1e-12f)));
    }
    __syncthreads();
    // logits: 64 groups of 8 threads; ALL threads run the shfl (full-warp
    // convergence), groups >= NEXP compute zeros and discard.
    int g = t >> 3, lg = t & 7;
    float acc = 0.f;
    if (g < NEXP) {
        #pragma unroll
        for (int i = 0; i < 32; i++) {
            int k = lg + i * 8;
            acc = fmaf(samp[k], w_gate[k * NEXP + g], acc);
        }
    }
    acc += __shfl_down_sync(0xffffffffu, acc, 4, 8);
    acc += __shfl_down_sync(0xffffffffu, acc, 2, 8);
    acc += __shfl_down_sync(0xffffffffu, acc, 1, 8);
    if (lg == 0 && g < NEXP) slog[g] = acc;
    __syncthreads();
    if (t == 0) {
        float v[NEXP];
        for (int e = 0; e < NEXP; e++) v[e] = slog[e];
        int   idx[TOPK];
        float val[TOPK];
        for (int tt = 0; tt < TOPK; tt++) {
            int bi = 0; float bv = v[0];
            for (int e = 1; e < NEXP; e++) if (v[e] > bv) { bv = v[e]; bi = e; }
            idx[tt] = bi; val[tt] = bv; v[bi] = -3.4e38f;
        }
        float mx = val[0], sum = 0.f, ex[TOPK];
        for (int tt = 0; tt < TOPK; tt++) { ex[tt] = expf(val[tt] - mx); sum += ex[tt]; }
        for (int e = 0; e < NEXP; e++) { gates_out[b * NEXP + e] = 0.f; g_mask[b][e] = 0.f; }
        for (int tt = 0; tt < TOPK; tt++) {
            gates_out[b * NEXP + idx[tt]] = ex[tt] / sum;
            g_mask[b][idx[tt]] = 1.0f;
        }
    }
}

// ---------------- K5: main patch-embedding / zero-fill ----------------
// grid (1657, 8, 2): x = patch-row (reversed: big p first), y = batch,
// z = d-half (0 -> d in [0,256), 1 -> d in [256,512)). 256 threads, 1 d-col each.
__global__ void __launch_bounds__(256)
embed_kernel(const float* __restrict__ x, const float* __restrict__ Wv,
             float* __restrict__ out) {
    const int r = (TOTROWS - 1) - blockIdx.x;     // largest p scheduled first
    const int b = blockIdx.y;
    const int z = blockIdx.z;
    const int tid = threadIdx.x;

    // expert lookup (constant-mem scan, uniform)
    int e = 0;
    while (c_OFF[e + 1] <= r) e++;
    const int p = c_P[e];
    const int j = r - c_OFF[e];

    const size_t cstride = (size_t)TOTROWS * DMODEL;
    float* outbase = out + ((size_t)(b * NFEAT) * TOTROWS + r) * DMODEL + z * 256;

    if (g_mask[b][e] == 0.f) {
        // zero-fill 16 rows x 256 cols, float4
        float4 zz = make_float4(0.f, 0.f, 0.f, 0.f);
        #pragma unroll
        for (int idx = tid; idx < NFEAT * 64; idx += 256) {
            int c = idx >> 6, v = idx & 63;
            *(float4*)(outbase + (size_t)c * cstride + v * 4) = zz;
        }
        return;
    }

    extern __shared__ float xsm[];                // p*16 floats (<=32KB)
    {
        const float4* x4 = (const float4*)x;
        float4* xsm4 = (float4*)xsm;
        for (int idx = tid; idx < p * 4; idx += 256) {
            int q = idx >> 2, v = idx & 3;
            int l = j * p + q; if (l > SEQL - 1) l = SEQL - 1;   // edge pad
            xsm4[idx] = x4[(((size_t)b * SEQL + l) << 2) + v];
        }
    }
    __syncthreads();

    float acc[NFEAT];
    #pragma unroll
    for (int c = 0; c < NFEAT; c++) acc[c] = 0.f;

    const float* wv = Wv + (size_t)e * SEQL * DMODEL + z * 256 + tid;
    for (int q = 0; q < p; q++) {
        float w = wv[(size_t)q * DMODEL];
        const float* xq = xsm + q * NFEAT;
        #pragma unroll
        for (int c = 0; c < NFEAT; c++) acc[c] = fmaf(xq[c], w, acc[c]);
    }

    if (z == 0) {
        #pragma unroll
        for (int c = 0; c < NFEAT; c++)
            outbase[(size_t)c * cstride + tid] = acc[c] + g_feat[c][tid];
    } else {
        float pe = g_pos[j][tid];
        #pragma unroll
        for (int c = 0; c < NFEAT; c++)
            outbase[(size_t)c * cstride + tid] = acc[c] + pe;
    }
}

// ---------------- launch ----------------
extern "C" void kernel_launch(void* const* d_in, const int* in_sizes, int n_in,
                              void* d_out, int out_size) {
    const float* x       = (const float*)d_in[0];
    const float* w_start = (const float*)d_in[1];
    const float* b_start = (const float*)d_in[2];
    const float* w1      = (const float*)d_in[3];
    const float* b1      = (const float*)d_in[4];
    const float* w2      = (const float*)d_in[5];
    const float* b2      = (const float*)d_in[6];
    const float* w_gate  = (const float*)d_in[7];
    const float* Wv      = (const float*)d_in[8];
    float* out = (float*)d_out;
    float* gates_out = out + EMB_ELEMS;

    gate1_pos_kernel<<<8 + 136, 512>>>(x, w_start, b_start);
    mlp1_part_kernel<<<dim3(HID / 256, KS1), 256>>>(w1);
    mlp2_part_kernel<<<KS2, 256>>>(w2, b1);
    gate2_kernel<<<BATCH, 512>>>(b2, w_gate, gates_out);
    embed_kernel<<<dim3(TOTROWS, BATCH, 2), 256, 32768>>>(x, Wv, out);
}